// round 9
// baseline (speedup 1.0000x reference)
#include <cuda_runtime.h>
#include <math.h>

#define NB 148
#define THREADS 512
#define BATCH 64
#define NPG 9
#define NTOT (BATCH*NPG)   // 576
#define H 128
#define K1 1801
#define O1 900
#define O2 100
#define ASL 243
#define NT1 15             // 15 n-tiles x 64 outs
#define KS1 9
#define KC1 201            // 9*201 = 1809 >= 1801
#define KS2 16
#define KC2 57             // 16*57 = 912 >= 900

// scratch (no allocation allowed)
__device__ float g_s1_part[KS1 * BATCH * O1];
__device__ float g_s2_part[KS2 * BATCH * O2];
__device__ float g_Ai[NTOT * H];
__device__ float g_Bj[NTOT * H];
__device__ unsigned g_count = 0;
__device__ unsigned g_gen = 0;

__device__ __forceinline__ void grid_barrier() {
    __syncthreads();
    __threadfence();
    if (threadIdx.x == 0) {
        unsigned gen = *(volatile unsigned*)&g_gen;
        if (atomicAdd(&g_count, 1u) == NB - 1) {
            g_count = 0;
            __threadfence();
            atomicAdd(&g_gen, 1u);
        } else {
            while (*(volatile unsigned*)&g_gen == gen) __nanosleep(32);
        }
    }
    __syncthreads();
}

// ---- packed f32x2 helpers (Blackwell FFMA2) ----
__device__ __forceinline__ unsigned long long pk2(float x, float y) {
    unsigned long long r;
    asm("mov.b64 %0, {%1, %2};" : "=l"(r) : "f"(x), "f"(y));
    return r;
}
__device__ __forceinline__ void fma2(unsigned long long& a,
                                     unsigned long long x, unsigned long long y) {
    asm("fma.rn.f32x2 %0, %1, %2, %0;" : "+l"(a) : "l"(x), "l"(y));
}
__device__ __forceinline__ float2 upk(unsigned long long v) {
    float2 f;
    asm("mov.b64 {%0, %1}, %2;" : "=f"(f.x), "=f"(f.y) : "l"(v));
    return f;
}

// One 32-row x 64-col tile of [Ai|Bj] = relu(nf) @ Wa2[0:256 rows]  (512 thr)
__device__ __forceinline__ void ab_task(int task, int t, float* buf,
                                        const float* __restrict__ nf,
                                        const float* __restrict__ Wa2) {
    float (*As)[128] = (float (*)[128])buf;            // 32x128
    float (*Bs)[64]  = (float (*)[64])(buf + 4096);    // 128x64
    const int mt = task % 18, nty = task / 18;
    const int m0 = mt * 32;
    const int n0 = nty * 64;
    const int woff = (nty >= 2) ? (H * H - H) : 0;
    for (int idx = t; idx < 32 * 128; idx += THREADS) {
        int r = idx >> 7, k = idx & 127;
        As[r][k] = fmaxf(nf[(m0 + r) * H + k], 0.f);
    }
    for (int idx = t; idx < 128 * 64; idx += THREADS) {
        int k = idx >> 6, c = idx & 63;
        Bs[k][c] = Wa2[k * H + n0 + c + woff];
    }
    __syncthreads();
    const int c = t & 63, r0 = t >> 6;   // 8 row groups, rows r0+8i
    unsigned long long acc2[4][2];
#pragma unroll
    for (int i = 0; i < 4; i++) { acc2[i][0] = 0ull; acc2[i][1] = 0ull; }
#pragma unroll 8
    for (int k = 0; k < 128; k += 4) {
        unsigned long long bp0 = pk2(Bs[k][c], Bs[k + 1][c]);
        unsigned long long bp1 = pk2(Bs[k + 2][c], Bs[k + 3][c]);
#pragma unroll
        for (int i = 0; i < 4; i++) {
            float4 a = *(const float4*)&As[r0 + 8 * i][k];
            fma2(acc2[i][0], pk2(a.x, a.y), bp0);
            fma2(acc2[i][1], pk2(a.z, a.w), bp1);
        }
    }
    float* dst = (nty < 2) ? g_Ai : g_Bj;
    const int col = (nty < 2) ? (n0 + c) : (n0 - 128 + c);
#pragma unroll
    for (int i = 0; i < 4; i++) {
        float2 u0 = upk(acc2[i][0]), u1 = upk(acc2[i][1]);
        dst[(m0 + r0 + 8 * i) * H + col] = (u0.x + u0.y) + (u1.x + u1.y);
    }
}

__global__ __launch_bounds__(THREADS, 1)
void fused_kernel(const float* __restrict__ nf, const float* __restrict__ spec,
                  const float* __restrict__ mask, const int* __restrict__ imask,
                  const float* __restrict__ W1, const float* __restrict__ b1,
                  const float* __restrict__ W2, const float* __restrict__ b2,
                  const float* __restrict__ Wv1, const float* __restrict__ bv1,
                  const float* __restrict__ Wv2, const float* __restrict__ bv2,
                  const float* __restrict__ Wa2, const float* __restrict__ ba2,
                  const float* __restrict__ Wf, const float* __restrict__ bf,
                  float* __restrict__ out) {
    __shared__ __align__(16) float buf[12288];   // 48KB, reused per phase
    const int t = threadIdx.x;
    const int bid = blockIdx.x;

    // ===== Phase 1: gemm1 (135 blocks, dbl-buffer 1-sync, FFMA2) + 13 ab =====
    if (bid < NT1 * KS1) {
        const int nt = bid / KS1, ks = bid % KS1;
        const int og = t & 31;
        const int bg = t >> 5;
        const int o0 = nt * 64 + og * 2;
        const int b0 = bg * 4;
        const int kbeg = ks * KC1;
        const int kend = min(kbeg + KC1, K1);
        const int nch = (kend - kbeg + 31) >> 5;
        // double buffers: sp[p]=buf+p*4352, wt[p]=sp+2176, stride 68

        const int kk_s = t & 31;
        const int bb_s = t >> 5;
        const int kk_w = t >> 6;
        const int oo_w = t & 63;
        const int ow_g = nt * 64 + oo_w;
        const bool wok = (ow_g < O1);

        float rsv[4], rwv[4];
        {
            const int k0 = kbeg;
            const int klen = kend - k0;
#pragma unroll
            for (int j = 0; j < 4; j++)
                rsv[j] = (kk_s < klen) ? spec[(bb_s + 16 * j) * K1 + k0 + kk_s] : 0.f;
#pragma unroll
            for (int j = 0; j < 4; j++) {
                int kk = kk_w + 8 * j;
                rwv[j] = (kk < klen && wok) ? W1[(k0 + kk) * O1 + ow_g] : 0.f;
            }
        }
        unsigned long long acc00 = 0ull, acc01 = 0ull, acc10 = 0ull, acc11 = 0ull;

        for (int c = 0; c < nch; c++) {
            float* sp = buf + (c & 1) * 4352;
            float* wt = sp + 2176;
            // store regs for chunk c (other buffer than chunk c-1's compute)
#pragma unroll
            for (int j = 0; j < 4; j++)
                sp[kk_s * 68 + bb_s + 16 * j] = rsv[j];
#pragma unroll
            for (int j = 0; j < 4; j++)
                wt[(kk_w + 8 * j) * 68 + oo_w] = rwv[j];
            __syncthreads();
            if (c + 1 < nch) {   // prefetch next chunk during compute
                const int k0 = kbeg + (c + 1) * 32;
                const int klen = kend - k0;
#pragma unroll
                for (int j = 0; j < 4; j++)
                    rsv[j] = (kk_s < klen) ? spec[(bb_s + 16 * j) * K1 + k0 + kk_s] : 0.f;
#pragma unroll
                for (int j = 0; j < 4; j++) {
                    int kk = kk_w + 8 * j;
                    rwv[j] = (kk < klen && wok) ? W1[(k0 + kk) * O1 + ow_g] : 0.f;
                }
            }
#pragma unroll
            for (int kk = 0; kk < 32; kk++) {
                float4 s4 = *(const float4*)(sp + kk * 68 + b0);   // warp bcast
                float2 w2 = *(const float2*)(wt + kk * 68 + og * 2);
                unsigned long long a01 = pk2(s4.x, s4.y);
                unsigned long long a23 = pk2(s4.z, s4.w);
                unsigned long long w00 = pk2(w2.x, w2.x);
                unsigned long long w11 = pk2(w2.y, w2.y);
                fma2(acc00, a01, w00);
                fma2(acc10, a23, w00);
                fma2(acc01, a01, w11);
                fma2(acc11, a23, w11);
            }
        }
        float* dst = g_s1_part + ks * (BATCH * O1);
        float2 u00 = upk(acc00), u10 = upk(acc10), u01 = upk(acc01), u11 = upk(acc11);
        if (o0 + 1 < O1) {
            dst[(b0 + 0) * O1 + o0] = u00.x; dst[(b0 + 0) * O1 + o0 + 1] = u01.x;
            dst[(b0 + 1) * O1 + o0] = u00.y; dst[(b0 + 1) * O1 + o0 + 1] = u01.y;
            dst[(b0 + 2) * O1 + o0] = u10.x; dst[(b0 + 2) * O1 + o0 + 1] = u11.x;
            dst[(b0 + 3) * O1 + o0] = u10.y; dst[(b0 + 3) * O1 + o0 + 1] = u11.y;
        } else if (o0 < O1) {
            dst[(b0 + 0) * O1 + o0] = u00.x;
            dst[(b0 + 1) * O1 + o0] = u00.y;
            dst[(b0 + 2) * O1 + o0] = u10.x;
            dst[(b0 + 3) * O1 + o0] = u10.y;
        }
    } else {
        ab_task(bid - NT1 * KS1, t, buf, nf, Wa2);   // tasks 0..12
    }

    grid_barrier();

    // ===== Phase 2: gemm2 with W2 staged in smem (blocks 0-63) + ab 13-71 =====
    if (bid < 64) {
        const int nt = bid & 3, ks = bid >> 2;
        const int o = nt * 32 + (t & 31);
        const int bg = t >> 5;
        const int b0 = bg * 4;
        const int kbeg = ks * KC2;
        const int kend = min(kbeg + KC2, O1);
        const int klen = kend - kbeg;
        float* s1r = buf;                         // [64][60]
        float* w2s = buf + 3840;                  // [57][33]
        for (int idx = t; idx < KC2 * 32; idx += THREADS) {
            int row = idx >> 5, col = idx & 31;
            int go = nt * 32 + col;
            w2s[row * 33 + col] = (row < klen && go < O2)
                                  ? W2[(kbeg + row) * O2 + go] : 0.f;
        }
        for (int idx = t; idx < 64 * KC2; idx += THREADS) {
            int b = idx / KC2, kk = idx - b * KC2;
            float v = 0.f;
            if (kk < klen) {
                int gk = kbeg + kk;
                v = b1[gk];
#pragma unroll
                for (int c = 0; c < KS1; c++)
                    v += g_s1_part[c * (BATCH * O1) + b * O1 + gk];
                v = fmaxf(v, 0.f);
            }
            s1r[b * 60 + kk] = v;
        }
        __syncthreads();
        float acc[4] = {0.f, 0.f, 0.f, 0.f};
        const float* sb = s1r + b0 * 60;
        const int lane = t & 31;
#pragma unroll 4
        for (int kk = 0; kk < klen; kk++) {
            float w = w2s[kk * 33 + lane];
            acc[0] += sb[kk] * w;
            acc[1] += sb[60 + kk] * w;
            acc[2] += sb[120 + kk] * w;
            acc[3] += sb[180 + kk] * w;
        }
        if (o < O2) {
#pragma unroll
            for (int n = 0; n < 4; n++)
                g_s2_part[ks * (BATCH * O2) + (b0 + n) * O2 + o] = acc[n];
        }
    } else if (bid < 64 + 59) {
        ab_task(13 + (bid - 64), t, buf, nf, Wa2);   // tasks 13..71
    }

    grid_barrier();

    // ===== Phase 3: per-graph; latency chains k-split over 512 threads =====
    if (bid < 64) {
        const int b = bid;
        const int lane = t & 31, w = t >> 5;
        float* ss   = buf;            // 100   [0,128)
        float* x    = buf + 128;      // 228   [128,384)
        float* Dc   = buf + 384;      // 128
        float* hred = buf + 512;      // 64
        float* As   = buf + 640;      // 9*132
        float* Bs   = buf + 1856;     // 9*132
        float* Wft  = buf + 3072;     // 384 (bond-major)
        float* fp2  = buf + 3456;     // 486
        float* fp   = buf + 3968;     // 243
        float* Dpart= buf + 4224;     // 512
        float* Vpart= buf + 4736;     // 512
        float* red  = buf + 5248;     // 16
        float* rs2  = buf + 5280;     // 2

        if (t < O2) {
            float a = b2[t];
#pragma unroll
            for (int c = 0; c < KS2; c++)
                a += g_s2_part[c * (BATCH * O2) + b * O2 + t];
            ss[t] = fmaxf(a, 0.f);
        }
        for (int idx = t; idx < NPG * H; idx += THREADS) {
            int i = idx >> 7, h = idx & 127;
            As[i * 132 + h] = g_Ai[(b * NPG + i) * H + h];
            Bs[i * 132 + h] = g_Bj[(b * NPG + i) * H + h];
        }
        for (int idx = t; idx < H * 3; idx += THREADS)
            Wft[(idx % 3) * H + idx / 3] = Wf[idx];
        if (t < H) {
            float sum = 0.f;
#pragma unroll
            for (int i = 0; i < NPG; i++) sum += nf[(b * NPG + i) * H + t];
            x[t] = sum;
        }
        __syncthreads();
        if (t >= H && t < H + O2) x[t] = ss[t - H];
        __syncthreads();

        // D partials: 128 outs x 4 k-splits of 25
        {
            const int o = t & 127, q = t >> 7;
            const int kb = q * 25;
            float d = 0.f;
#pragma unroll
            for (int kk = 0; kk < 25; kk++)
                d += ss[kb + kk] * Wa2[(2 * H + kb + kk) * H + o];
            Dpart[q * H + o] = d;
        }
        // value partials: 64 outs x 8 k-splits of 29
        {
            const int o = t & 63, q = t >> 6;
            const int kb = q * 29;
            const int kl = min(29, 228 - kb);
            float v = 0.f;
            for (int kk = 0; kk < kl; kk++)
                v += x[kb + kk] * Wv1[(kb + kk) * 64 + o];
            Vpart[q * 64 + o] = v;
        }
        __syncthreads();
        if (t < H)
            Dc[t] = ba2[t] + Dpart[t] + Dpart[H + t] + Dpart[2 * H + t] + Dpart[3 * H + t];
        if (t < 64) {
            float a = bv1[t];
#pragma unroll
            for (int q = 0; q < 8; q++) a += Vpart[q * 64 + t];
            hred[t] = fmaxf(a, 0.f) * Wv2[t];
        }
        __syncthreads();

        // pair logits: 486 threads = 243 outputs x 2 h-halves
        if (t < 486) {
            const int half = (t >= ASL) ? 1 : 0;
            const int pi = t - ASL * half;
            const int pair = pi / 3, bond = pi - pair * 3;
            const int i = pair / NPG, j = pair - i * NPG;
            const float4* Ap = (const float4*)(As + i * 132) + half * 16;
            const float4* Bp = (const float4*)(Bs + j * 132) + half * 16;
            const float4* Dp = (const float4*)Dc + half * 16;
            const float4* Wp = (const float4*)(Wft + bond * H) + half * 16;
            float a = 0.f;
#pragma unroll
            for (int q = 0; q < 16; q++) {
                float4 av = Ap[q], bv = Bp[q], dv = Dp[q], wv = Wp[q];
                a += fmaxf(av.x + bv.x + dv.x, 0.f) * wv.x
                   + fmaxf(av.y + bv.y + dv.y, 0.f) * wv.y
                   + fmaxf(av.z + bv.z + dv.z, 0.f) * wv.z
                   + fmaxf(av.w + bv.w + dv.w, 0.f) * wv.w;
            }
            fp2[t] = a;
        }
        __syncthreads();
        if (t < ASL) fp[t] = fp2[t] + fp2[ASL + t] + bf[t % 3];
        __syncthreads();

        float g = -INFINITY;
        if (t < ASL) g = fp[imask[b * ASL + t]] + mask[b * ASL + t];
        float v = g;
#pragma unroll
        for (int off = 16; off; off >>= 1) v = fmaxf(v, __shfl_xor_sync(0xffffffffu, v, off));
        if (lane == 0) red[w] = v;
        __syncthreads();
        if (t == 0) {
            float m = red[0];
#pragma unroll
            for (int i = 1; i < 16; i++) m = fmaxf(m, red[i]);
            rs2[0] = m;
        }
        __syncthreads();
        float e = (t < ASL) ? __expf(g - rs2[0]) : 0.f;
        v = e;
#pragma unroll
        for (int off = 16; off; off >>= 1) v += __shfl_xor_sync(0xffffffffu, v, off);
        if (lane == 0) red[w] = v;
        __syncthreads();
        if (t == 0) {
            float s = 0.f;
#pragma unroll
            for (int i = 0; i < 16; i++) s += red[i];
            rs2[1] = s;
            float vo = bv2[0];
#pragma unroll
            for (int k = 0; k < 64; k++) vo += hred[k];
            out[BATCH * ASL + b] = vo;
        }
        __syncthreads();
        if (t < ASL) out[b * ASL + t] = e / rs2[1];
    }
}

extern "C" void kernel_launch(void* const* d_in, const int* in_sizes, int n_in,
                              void* d_out, int out_size) {
    const float* nf   = (const float*)d_in[0];
    const float* spec = (const float*)d_in[1];
    const float* mask = (const float*)d_in[3];
    const int*   imask= (const int*)  d_in[4];
    const float* W1   = (const float*)d_in[5];
    const float* b1   = (const float*)d_in[6];
    const float* W2   = (const float*)d_in[7];
    const float* b2   = (const float*)d_in[8];
    const float* Wv1  = (const float*)d_in[9];
    const float* bv1  = (const float*)d_in[10];
    const float* Wv2  = (const float*)d_in[11];
    const float* bv2  = (const float*)d_in[12];
    const float* Wa2  = (const float*)d_in[13];
    const float* ba2  = (const float*)d_in[14];
    const float* Wf   = (const float*)d_in[15];
    const float* bf   = (const float*)d_in[16];
    float* out = (float*)d_out;

    fused_kernel<<<NB, THREADS>>>(nf, spec, mask, imask, W1, b1, W2, b2,
                                  Wv1, bv1, Wv2, bv2, Wa2, ba2, Wf, bf, out);
}

// round 10
// speedup vs baseline: 1.0211x; 1.0211x over previous
#include <cuda_runtime.h>
#include <math.h>

#define NB 148
#define THREADS 512
#define BATCH 64
#define NPG 9
#define NTOT (BATCH*NPG)   // 576
#define H 128
#define K1 1801
#define O1 900
#define O2 100
#define ASL 243
#define NT1 15             // 15 n-tiles x 64 outs
#define KS1 9
#define KC1 201            // 9*201 = 1809 >= 1801
#define KS2 16
#define KC2 57             // 16*57 = 912 >= 900

// scratch (no allocation allowed)
__device__ float g_s1_part[KS1 * BATCH * O1];
__device__ float g_s2_part[KS2 * BATCH * O2];
__device__ float g_Ai[NTOT * H];
__device__ float g_Bj[NTOT * H];
__device__ unsigned g_count = 0;
__device__ unsigned g_gen = 0;

__device__ __forceinline__ void grid_barrier() {
    __syncthreads();
    __threadfence();
    if (threadIdx.x == 0) {
        unsigned gen = *(volatile unsigned*)&g_gen;
        if (atomicAdd(&g_count, 1u) == NB - 1) {
            g_count = 0;
            __threadfence();
            atomicAdd(&g_gen, 1u);
        } else {
            while (*(volatile unsigned*)&g_gen == gen) __nanosleep(32);
        }
    }
    __syncthreads();
}

// ---- packed f32x2 helpers (Blackwell FFMA2) ----
__device__ __forceinline__ unsigned long long pkdup(float x) {
    unsigned long long r;
    asm("mov.b64 %0, {%1, %1};" : "=l"(r) : "f"(x));
    return r;
}
__device__ __forceinline__ void fma2(unsigned long long& a,
                                     unsigned long long x, unsigned long long y) {
    asm("fma.rn.f32x2 %0, %1, %2, %0;" : "+l"(a) : "l"(x), "l"(y));
}
__device__ __forceinline__ float2 upk(unsigned long long v) {
    float2 f;
    asm("mov.b64 {%0, %1}, %2;" : "=f"(f.x), "=f"(f.y) : "l"(v));
    return f;
}

// One 32-row x 64-col tile of [Ai|Bj] = relu(nf) @ Wa2[0:256 rows]  (512 thr)
// R8-proven scalar version.
__device__ __forceinline__ void ab_task(int task, int t, float* buf,
                                        const float* __restrict__ nf,
                                        const float* __restrict__ Wa2) {
    float (*As)[128] = (float (*)[128])buf;            // 32x128
    float (*Bs)[64]  = (float (*)[64])(buf + 4096);    // 128x64
    const int mt = task % 18, nty = task / 18;
    const int m0 = mt * 32;
    const int n0 = nty * 64;
    const int woff = (nty >= 2) ? (H * H - H) : 0;
    for (int idx = t; idx < 32 * 128; idx += THREADS) {
        int r = idx >> 7, k = idx & 127;
        As[r][k] = fmaxf(nf[(m0 + r) * H + k], 0.f);
    }
    for (int idx = t; idx < 128 * 64; idx += THREADS) {
        int k = idx >> 6, c = idx & 63;
        Bs[k][c] = Wa2[k * H + n0 + c + woff];
    }
    __syncthreads();
    const int c = t & 63, r0 = t >> 6;   // 8 row groups, rows r0+8i
    float acc[4] = {0.f, 0.f, 0.f, 0.f};
#pragma unroll 8
    for (int k = 0; k < 128; k += 4) {
        float b0v = Bs[k][c], b1v = Bs[k + 1][c];
        float b2v = Bs[k + 2][c], b3v = Bs[k + 3][c];
#pragma unroll
        for (int i = 0; i < 4; i++) {
            float4 a = *(const float4*)&As[r0 + 8 * i][k];
            acc[i] += a.x * b0v + a.y * b1v + a.z * b2v + a.w * b3v;
        }
    }
    float* dst = (nty < 2) ? g_Ai : g_Bj;
    const int col = (nty < 2) ? (n0 + c) : (n0 - 128 + c);
#pragma unroll
    for (int i = 0; i < 4; i++)
        dst[(m0 + r0 + 8 * i) * H + col] = acc[i];
}

__global__ __launch_bounds__(THREADS, 1)
void fused_kernel(const float* __restrict__ nf, const float* __restrict__ spec,
                  const float* __restrict__ mask, const int* __restrict__ imask,
                  const float* __restrict__ W1, const float* __restrict__ b1,
                  const float* __restrict__ W2, const float* __restrict__ b2,
                  const float* __restrict__ Wv1, const float* __restrict__ bv1,
                  const float* __restrict__ Wv2, const float* __restrict__ bv2,
                  const float* __restrict__ Wa2, const float* __restrict__ ba2,
                  const float* __restrict__ Wf, const float* __restrict__ bf,
                  float* __restrict__ out) {
    __shared__ __align__(16) float buf[12288];   // 48KB, reused per phase
    const int t = threadIdx.x;
    const int bid = blockIdx.x;

    // ===== Phase 1: gemm1 (135 blocks, R8 staging, FFMA2 inner) + 13 ab =====
    if (bid < NT1 * KS1) {
        const int nt = bid / KS1, ks = bid % KS1;
        const int og = t & 31;
        const int bg = t >> 5;
        const int o0 = nt * 64 + og * 2;
        const int b0 = bg * 4;
        const int kbeg = ks * KC1;
        const int kend = min(kbeg + KC1, K1);
        const int nch = (kend - kbeg + 31) >> 5;
        float* sp = buf;                     // [32][68]
        float* wt = buf + 32 * 68;           // [32][68]

        const int kk_s = t & 31;
        const int bb_s = t >> 5;
        const int kk_w = t >> 6;
        const int oo_w = t & 63;
        const int ow_g = nt * 64 + oo_w;
        const bool wok = (ow_g < O1);

        float rsv[4], rwv[4];
        {
            const int k0 = kbeg;
            const int klen = kend - k0;
#pragma unroll
            for (int j = 0; j < 4; j++)
                rsv[j] = (kk_s < klen) ? spec[(bb_s + 16 * j) * K1 + k0 + kk_s] : 0.f;
#pragma unroll
            for (int j = 0; j < 4; j++) {
                int kk = kk_w + 8 * j;
                rwv[j] = (kk < klen && wok) ? W1[(k0 + kk) * O1 + ow_g] : 0.f;
            }
        }
        unsigned long long acc00 = 0ull, acc10 = 0ull, acc01 = 0ull, acc11 = 0ull;
        // u64 view of this thread's spec pairs: sp + b0 is 16B-aligned (b0 = 4*bg)
        const unsigned long long* spq =
            (const unsigned long long*)(sp + b0);      // index kk*34 gives (b0,b1)

        for (int c = 0; c < nch; c++) {
            __syncthreads();
#pragma unroll
            for (int j = 0; j < 4; j++)
                sp[kk_s * 68 + bb_s + 16 * j] = rsv[j];
#pragma unroll
            for (int j = 0; j < 4; j++)
                wt[(kk_w + 8 * j) * 68 + oo_w] = rwv[j];
            __syncthreads();
            if (c + 1 < nch) {
                const int k0 = kbeg + (c + 1) * 32;
                const int klen = kend - k0;
#pragma unroll
                for (int j = 0; j < 4; j++)
                    rsv[j] = (kk_s < klen) ? spec[(bb_s + 16 * j) * K1 + k0 + kk_s] : 0.f;
#pragma unroll
                for (int j = 0; j < 4; j++) {
                    int kk = kk_w + 8 * j;
                    rwv[j] = (kk < klen && wok) ? W1[(k0 + kk) * O1 + ow_g] : 0.f;
                }
            }
#pragma unroll
            for (int kk = 0; kk < 32; kk++) {
                unsigned long long s01 = spq[kk * 34];       // (spec[b0], spec[b1])
                unsigned long long s23 = spq[kk * 34 + 1];   // (spec[b2], spec[b3])
                float2 w2 = *(const float2*)(wt + kk * 68 + og * 2);
                unsigned long long w00 = pkdup(w2.x);
                unsigned long long w11 = pkdup(w2.y);
                fma2(acc00, s01, w00);
                fma2(acc10, s23, w00);
                fma2(acc01, s01, w11);
                fma2(acc11, s23, w11);
            }
        }
        float* dst = g_s1_part + ks * (BATCH * O1);
        float2 u00 = upk(acc00), u10 = upk(acc10), u01 = upk(acc01), u11 = upk(acc11);
        if (o0 + 1 < O1) {
            dst[(b0 + 0) * O1 + o0] = u00.x; dst[(b0 + 0) * O1 + o0 + 1] = u01.x;
            dst[(b0 + 1) * O1 + o0] = u00.y; dst[(b0 + 1) * O1 + o0 + 1] = u01.y;
            dst[(b0 + 2) * O1 + o0] = u10.x; dst[(b0 + 2) * O1 + o0 + 1] = u11.x;
            dst[(b0 + 3) * O1 + o0] = u10.y; dst[(b0 + 3) * O1 + o0 + 1] = u11.y;
        } else if (o0 < O1) {
            dst[(b0 + 0) * O1 + o0] = u00.x;
            dst[(b0 + 1) * O1 + o0] = u00.y;
            dst[(b0 + 2) * O1 + o0] = u10.x;
            dst[(b0 + 3) * O1 + o0] = u10.y;
        }
    } else {
        ab_task(bid - NT1 * KS1, t, buf, nf, Wa2);   // tasks 0..12
    }

    grid_barrier();

    // ===== Phase 2: gemm2 with W2 staged in smem (blocks 0-63) + ab 13-71 =====
    if (bid < 64) {
        const int nt = bid & 3, ks = bid >> 2;
        const int o = nt * 32 + (t & 31);
        const int bg = t >> 5;
        const int b0 = bg * 4;
        const int kbeg = ks * KC2;
        const int kend = min(kbeg + KC2, O1);
        const int klen = kend - kbeg;
        float* s1r = buf;                         // [64][60]
        float* w2s = buf + 3840;                  // [57][33]
        for (int idx = t; idx < KC2 * 32; idx += THREADS) {
            int row = idx >> 5, col = idx & 31;
            int go = nt * 32 + col;
            w2s[row * 33 + col] = (row < klen && go < O2)
                                  ? W2[(kbeg + row) * O2 + go] : 0.f;
        }
        for (int idx = t; idx < 64 * KC2; idx += THREADS) {
            int b = idx / KC2, kk = idx - b * KC2;
            float v = 0.f;
            if (kk < klen) {
                int gk = kbeg + kk;
                v = b1[gk];
#pragma unroll
                for (int c = 0; c < KS1; c++)
                    v += g_s1_part[c * (BATCH * O1) + b * O1 + gk];
                v = fmaxf(v, 0.f);
            }
            s1r[b * 60 + kk] = v;
        }
        __syncthreads();
        float acc[4] = {0.f, 0.f, 0.f, 0.f};
        const float* sb = s1r + b0 * 60;
        const int lane = t & 31;
#pragma unroll 4
        for (int kk = 0; kk < klen; kk++) {
            float w = w2s[kk * 33 + lane];
            acc[0] += sb[kk] * w;
            acc[1] += sb[60 + kk] * w;
            acc[2] += sb[120 + kk] * w;
            acc[3] += sb[180 + kk] * w;
        }
        if (o < O2) {
#pragma unroll
            for (int n = 0; n < 4; n++)
                g_s2_part[ks * (BATCH * O2) + (b0 + n) * O2 + o] = acc[n];
        }
    } else if (bid < 64 + 59) {
        ab_task(13 + (bid - 64), t, buf, nf, Wa2);   // tasks 13..71
    }

    grid_barrier();

    // ===== Phase 3: per-graph; latency chains k-split over 512 threads =====
    if (bid < 64) {
        const int b = bid;
        const int lane = t & 31, w = t >> 5;
        float* ss   = buf;            // 100   [0,128)
        float* x    = buf + 128;      // 228   [128,384)
        float* Dc   = buf + 384;      // 128
        float* hred = buf + 512;      // 64
        float* As   = buf + 640;      // 9*132
        float* Bs   = buf + 1856;     // 9*132
        float* Wft  = buf + 3072;     // 384 (bond-major)
        float* fp2  = buf + 3456;     // 486
        float* fp   = buf + 3968;     // 243
        float* Dpart= buf + 4224;     // 512
        float* Vpart= buf + 4736;     // 512
        float* red  = buf + 5248;     // 16
        float* rs2  = buf + 5280;     // 2

        if (t < O2) {
            float a = b2[t];
#pragma unroll
            for (int c = 0; c < KS2; c++)
                a += g_s2_part[c * (BATCH * O2) + b * O2 + t];
            ss[t] = fmaxf(a, 0.f);
        }
        for (int idx = t; idx < NPG * H; idx += THREADS) {
            int i = idx >> 7, h = idx & 127;
            As[i * 132 + h] = g_Ai[(b * NPG + i) * H + h];
            Bs[i * 132 + h] = g_Bj[(b * NPG + i) * H + h];
        }
        for (int idx = t; idx < H * 3; idx += THREADS)
            Wft[(idx % 3) * H + idx / 3] = Wf[idx];
        if (t < H) {
            float sum = 0.f;
#pragma unroll
            for (int i = 0; i < NPG; i++) sum += nf[(b * NPG + i) * H + t];
            x[t] = sum;
        }
        __syncthreads();
        if (t >= H && t < H + O2) x[t] = ss[t - H];
        __syncthreads();

        // D partials: 128 outs x 4 k-splits of 25
        {
            const int o = t & 127, q = t >> 7;
            const int kb = q * 25;
            float d = 0.f;
#pragma unroll
            for (int kk = 0; kk < 25; kk++)
                d += ss[kb + kk] * Wa2[(2 * H + kb + kk) * H + o];
            Dpart[q * H + o] = d;
        }
        // value partials: 64 outs x 8 k-splits of 29
        {
            const int o = t & 63, q = t >> 6;
            const int kb = q * 29;
            const int kl = min(29, 228 - kb);
            float v = 0.f;
            for (int kk = 0; kk < kl; kk++)
                v += x[kb + kk] * Wv1[(kb + kk) * 64 + o];
            Vpart[q * 64 + o] = v;
        }
        __syncthreads();
        if (t < H)
            Dc[t] = ba2[t] + Dpart[t] + Dpart[H + t] + Dpart[2 * H + t] + Dpart[3 * H + t];
        if (t < 64) {
            float a = bv1[t];
#pragma unroll
            for (int q = 0; q < 8; q++) a += Vpart[q * 64 + t];
            hred[t] = fmaxf(a, 0.f) * Wv2[t];
        }
        __syncthreads();

        // pair logits: 486 threads = 243 outputs x 2 h-halves
        if (t < 486) {
            const int half = (t >= ASL) ? 1 : 0;
            const int pi = t - ASL * half;
            const int pair = pi / 3, bond = pi - pair * 3;
            const int i = pair / NPG, j = pair - i * NPG;
            const float4* Ap = (const float4*)(As + i * 132) + half * 16;
            const float4* Bp = (const float4*)(Bs + j * 132) + half * 16;
            const float4* Dp = (const float4*)Dc + half * 16;
            const float4* Wp = (const float4*)(Wft + bond * H) + half * 16;
            float a = 0.f;
#pragma unroll
            for (int q = 0; q < 16; q++) {
                float4 av = Ap[q], bv = Bp[q], dv = Dp[q], wv = Wp[q];
                a += fmaxf(av.x + bv.x + dv.x, 0.f) * wv.x
                   + fmaxf(av.y + bv.y + dv.y, 0.f) * wv.y
                   + fmaxf(av.z + bv.z + dv.z, 0.f) * wv.z
                   + fmaxf(av.w + bv.w + dv.w, 0.f) * wv.w;
            }
            fp2[t] = a;
        }
        __syncthreads();
        if (t < ASL) fp[t] = fp2[t] + fp2[ASL + t] + bf[t % 3];
        __syncthreads();

        float g = -INFINITY;
        if (t < ASL) g = fp[imask[b * ASL + t]] + mask[b * ASL + t];
        float v = g;
#pragma unroll
        for (int off = 16; off; off >>= 1) v = fmaxf(v, __shfl_xor_sync(0xffffffffu, v, off));
        if (lane == 0) red[w] = v;
        __syncthreads();
        if (t == 0) {
            float m = red[0];
#pragma unroll
            for (int i = 1; i < 16; i++) m = fmaxf(m, red[i]);
            rs2[0] = m;
        }
        __syncthreads();
        float e = (t < ASL) ? __expf(g - rs2[0]) : 0.f;
        v = e;
#pragma unroll
        for (int off = 16; off; off >>= 1) v += __shfl_xor_sync(0xffffffffu, v, off);
        if (lane == 0) red[w] = v;
        __syncthreads();
        if (t == 0) {
            float s = 0.f;
#pragma unroll
            for (int i = 0; i < 16; i++) s += red[i];
            rs2[1] = s;
            float vo = bv2[0];
#pragma unroll
            for (int k = 0; k < 64; k++) vo += hred[k];
            out[BATCH * ASL + b] = vo;
        }
        __syncthreads();
        if (t < ASL) out[b * ASL + t] = e / rs2[1];
    }
}

extern "C" void kernel_launch(void* const* d_in, const int* in_sizes, int n_in,
                              void* d_out, int out_size) {
    const float* nf   = (const float*)d_in[0];
    const float* spec = (const float*)d_in[1];
    const float* mask = (const float*)d_in[3];
    const int*   imask= (const int*)  d_in[4];
    const float* W1   = (const float*)d_in[5];
    const float* b1   = (const float*)d_in[6];
    const float* W2   = (const float*)d_in[7];
    const float* b2   = (const float*)d_in[8];
    const float* Wv1  = (const float*)d_in[9];
    const float* bv1  = (const float*)d_in[10];
    const float* Wv2  = (const float*)d_in[11];
    const float* bv2  = (const float*)d_in[12];
    const float* Wa2  = (const float*)d_in[13];
    const float* ba2  = (const float*)d_in[14];
    const float* Wf   = (const float*)d_in[15];
    const float* bf   = (const float*)d_in[16];
    float* out = (float*)d_out;

    fused_kernel<<<NB, THREADS>>>(nf, spec, mask, imask, W1, b1, W2, b2,
                                  Wv1, bv1, Wv2, bv2, Wa2, ba2, Wf, bf, out);
}

// round 11
// speedup vs baseline: 1.1279x; 1.1046x over previous
#include <cuda_runtime.h>
#include <math.h>

#define NB 148
#define THREADS 512
#define BATCH 64
#define NPG 9
#define NTOT (BATCH*NPG)   // 576
#define H 128
#define K1 1801
#define O1 900
#define O2 100
#define ASL 243
#define NT1 15             // 15 n-tiles x 64 outs
#define KS1 9
#define KC1 201            // 9*201 = 1809 >= 1801

// scratch (no allocation allowed)
__device__ float g_s1_part[KS1 * BATCH * O1];
__device__ unsigned g_count = 0;
__device__ unsigned g_gen = 0;

__device__ __forceinline__ void grid_barrier() {
    __syncthreads();
    __threadfence();
    if (threadIdx.x == 0) {
        unsigned gen = *(volatile unsigned*)&g_gen;
        if (atomicAdd(&g_count, 1u) == NB - 1) {
            g_count = 0;
            __threadfence();
            atomicAdd(&g_gen, 1u);
        } else {
            while (*(volatile unsigned*)&g_gen == gen) __nanosleep(32);
        }
    }
    __syncthreads();
}

__global__ __launch_bounds__(THREADS, 1)
void fused_kernel(const float* __restrict__ nf, const float* __restrict__ spec,
                  const float* __restrict__ mask, const int* __restrict__ imask,
                  const float* __restrict__ W1, const float* __restrict__ b1,
                  const float* __restrict__ W2, const float* __restrict__ b2,
                  const float* __restrict__ Wv1, const float* __restrict__ bv1,
                  const float* __restrict__ Wv2, const float* __restrict__ bv2,
                  const float* __restrict__ Wa2, const float* __restrict__ ba2,
                  const float* __restrict__ Wf, const float* __restrict__ bf,
                  float* __restrict__ out) {
    __shared__ __align__(16) float buf[12288];   // 48KB, reused per phase
    const int t = threadIdx.x;
    const int bid = blockIdx.x;

    // ===== Phase 1: gemm1 only (135 blocks; R8-proven scalar, reg-prefetch) =====
    if (bid < NT1 * KS1) {
        const int nt = bid / KS1, ks = bid % KS1;
        const int og = t & 31;
        const int bg = t >> 5;
        const int o0 = nt * 64 + og * 2;
        const int b0 = bg * 4;
        const int kbeg = ks * KC1;
        const int kend = min(kbeg + KC1, K1);
        const int nch = (kend - kbeg + 31) >> 5;
        float* sp = buf;                     // [32][68]
        float* wt = buf + 32 * 68;           // [32][68]

        const int kk_s = t & 31;
        const int bb_s = t >> 5;
        const int kk_w = t >> 6;
        const int oo_w = t & 63;
        const int ow_g = nt * 64 + oo_w;
        const bool wok = (ow_g < O1);

        float rsv[4], rwv[4];
        {
            const int k0 = kbeg;
            const int klen = kend - k0;
#pragma unroll
            for (int j = 0; j < 4; j++)
                rsv[j] = (kk_s < klen) ? spec[(bb_s + 16 * j) * K1 + k0 + kk_s] : 0.f;
#pragma unroll
            for (int j = 0; j < 4; j++) {
                int kk = kk_w + 8 * j;
                rwv[j] = (kk < klen && wok) ? W1[(k0 + kk) * O1 + ow_g] : 0.f;
            }
        }
        float a00 = 0.f, a01 = 0.f, a10 = 0.f, a11 = 0.f;
        float a20 = 0.f, a21 = 0.f, a30 = 0.f, a31 = 0.f;

        for (int c = 0; c < nch; c++) {
            __syncthreads();
#pragma unroll
            for (int j = 0; j < 4; j++)
                sp[kk_s * 68 + bb_s + 16 * j] = rsv[j];
#pragma unroll
            for (int j = 0; j < 4; j++)
                wt[(kk_w + 8 * j) * 68 + oo_w] = rwv[j];
            __syncthreads();
            if (c + 1 < nch) {
                const int k0 = kbeg + (c + 1) * 32;
                const int klen = kend - k0;
#pragma unroll
                for (int j = 0; j < 4; j++)
                    rsv[j] = (kk_s < klen) ? spec[(bb_s + 16 * j) * K1 + k0 + kk_s] : 0.f;
#pragma unroll
                for (int j = 0; j < 4; j++) {
                    int kk = kk_w + 8 * j;
                    rwv[j] = (kk < klen && wok) ? W1[(k0 + kk) * O1 + ow_g] : 0.f;
                }
            }
#pragma unroll
            for (int kk = 0; kk < 32; kk++) {
                float4 s4 = *(const float4*)(sp + kk * 68 + b0);
                float2 w2 = *(const float2*)(wt + kk * 68 + og * 2);
                a00 += s4.x * w2.x; a01 += s4.x * w2.y;
                a10 += s4.y * w2.x; a11 += s4.y * w2.y;
                a20 += s4.z * w2.x; a21 += s4.z * w2.y;
                a30 += s4.w * w2.x; a31 += s4.w * w2.y;
            }
        }
        float* dst = g_s1_part + ks * (BATCH * O1);
        if (o0 + 1 < O1) {
            dst[(b0 + 0) * O1 + o0] = a00; dst[(b0 + 0) * O1 + o0 + 1] = a01;
            dst[(b0 + 1) * O1 + o0] = a10; dst[(b0 + 1) * O1 + o0 + 1] = a11;
            dst[(b0 + 2) * O1 + o0] = a20; dst[(b0 + 2) * O1 + o0 + 1] = a21;
            dst[(b0 + 3) * O1 + o0] = a30; dst[(b0 + 3) * O1 + o0 + 1] = a31;
        } else if (o0 < O1) {
            dst[(b0 + 0) * O1 + o0] = a00;
            dst[(b0 + 1) * O1 + o0] = a10;
            dst[(b0 + 2) * O1 + o0] = a20;
            dst[(b0 + 3) * O1 + o0] = a30;
        }
    }
    // blocks 135..147 idle in phase 1

    grid_barrier();

    // ===== Phase 2: per-graph everything (64 blocks) =====
    if (bid < 64) {
        const int b = bid;
        const int lane = t & 31, w = t >> 5;
        // smem layout (floats)
        float* nfs_t = buf;            // [128][12] transposed relu(nf)  [0,1536)
        float* s1r   = buf + 1536;     // 900
        float* g2p   = buf + 2448;     // 2000 gemm2 partials [20][100]
        float* Pq    = buf + 4448;     // 2304 ab partials (q=1)
        float* As    = buf + 6752;     // 9*132
        float* Bs    = buf + 7940;     // 9*132
        float* Wft   = buf + 9128;     // 384 bond-major
        float* x     = buf + 9512;     // 228 (pad 256)
        float* ss    = buf + 9768;     // 100 (pad 128)
        float* Dc    = buf + 9896;     // 128
        float* hred  = buf + 10024;    // 64
        float* fp2   = buf + 10088;    // 486 (pad 512)
        float* fp    = buf + 10600;    // 243 (pad 256)
        float* Dpart = buf + 10856;    // 512
        float* Vpart = buf + 11368;    // 512
        float* red   = buf + 11880;    // 16
        float* rs2   = buf + 11896;    // 2

        // --- stage A: nfs_t, s1r (reduce+bias+relu), Wft, readout x[0:128]
        for (int idx = t; idx < NPG * H; idx += THREADS) {
            int i = idx >> 7, k = idx & 127;
            nfs_t[k * 12 + i] = fmaxf(nf[(b * NPG + i) * H + k], 0.f);
        }
        for (int idx = t; idx < O1; idx += THREADS) {
            float v = b1[idx];
#pragma unroll
            for (int c = 0; c < KS1; c++)
                v += g_s1_part[c * (BATCH * O1) + b * O1 + idx];
            s1r[idx] = fmaxf(v, 0.f);
        }
        for (int idx = t; idx < H * 3; idx += THREADS)
            Wft[(idx % 3) * H + idx / 3] = Wf[idx];
        if (t < H) {
            float sum = 0.f;
#pragma unroll
            for (int i = 0; i < NPG; i++) sum += nf[(b * NPG + i) * H + t];
            x[t] = sum;
        }
        __syncthreads();

        // --- stage B: ab partials (all threads) + gemm2 partials (t<500)
        {
            // ab: c = t&255 (Ai cols 0-127 / Bj cols 0-127), q = t>>8 -> k half
            const int c = t & 255, q = t >> 8;
            const int kb = q * 64;
            const float* wbase = Wa2 + ((c < 128) ? c : (H * H + (c - 128)));
            float accp[9];
#pragma unroll
            for (int i = 0; i < 9; i++) accp[i] = 0.f;
#pragma unroll 4
            for (int k = 0; k < 64; k++) {
                const int kg = kb + k;
                float wv = wbase[(size_t)kg * H];
                const float* nr = nfs_t + kg * 12;
                float4 n0 = *(const float4*)nr;
                float4 n1 = *(const float4*)(nr + 4);
                float n8 = nr[8];
                accp[0] += n0.x * wv; accp[1] += n0.y * wv;
                accp[2] += n0.z * wv; accp[3] += n0.w * wv;
                accp[4] += n1.x * wv; accp[5] += n1.y * wv;
                accp[6] += n1.z * wv; accp[7] += n1.w * wv;
                accp[8] += n8 * wv;
            }
            if (q == 0) {
                if (c < 128) {
#pragma unroll
                    for (int i = 0; i < 9; i++) As[i * 132 + c] = accp[i];
                } else {
#pragma unroll
                    for (int i = 0; i < 9; i++) Bs[i * 132 + c - 128] = accp[i];
                }
            } else {
#pragma unroll
                for (int i = 0; i < 9; i++) Pq[c * 9 + i] = accp[i];
            }
        }
        if (t < 500) {
            // gemm2 partial: 25 col-quads x 20 k-splits of 45
            const int oq = t % 25, q = t / 25;
            const int o4 = oq * 4, kb = q * 45;
            float4 acc = make_float4(0.f, 0.f, 0.f, 0.f);
#pragma unroll 5
            for (int kk = 0; kk < 45; kk++) {
                const int k = kb + kk;
                float4 wv = *(const float4*)(W2 + (size_t)k * O2 + o4);
                float s = s1r[k];
                acc.x += s * wv.x; acc.y += s * wv.y;
                acc.z += s * wv.z; acc.w += s * wv.w;
            }
            *(float4*)(g2p + q * O2 + o4) = acc;
        }
        __syncthreads();

        // --- stage C: ss reduce; combine ab partials into As/Bs
        if (t < O2) {
            float a = b2[t];
#pragma unroll
            for (int q = 0; q < 20; q++) a += g2p[q * O2 + t];
            ss[t] = fmaxf(a, 0.f);
        }
        for (int idx = t; idx < 2304; idx += THREADS) {
            int c = idx / 9, i = idx - c * 9;
            float add = Pq[idx];
            if (c < 128) As[i * 132 + c] += add;
            else         Bs[i * 132 + c - 128] += add;
        }
        __syncthreads();

        // --- stage D: x tail; D partials
        if (t < O2) x[H + t] = ss[t];
        {
            const int o = t & 127, q = t >> 7;
            const int kb = q * 25;
            float d = 0.f;
#pragma unroll
            for (int kk = 0; kk < 25; kk++)
                d += ss[kb + kk] * Wa2[(size_t)(2 * H + kb + kk) * H + o];
            Dpart[q * H + o] = d;
        }
        __syncthreads();

        // --- stage E: V partials; Dc
        {
            const int o = t & 63, q = t >> 6;
            const int kb = q * 29;
            const int kl = min(29, 228 - kb);
            float v = 0.f;
            for (int kk = 0; kk < kl; kk++)
                v += x[kb + kk] * Wv1[(size_t)(kb + kk) * 64 + o];
            Vpart[q * 64 + o] = v;
        }
        if (t < H)
            Dc[t] = ba2[t] + Dpart[t] + Dpart[H + t] + Dpart[2 * H + t] + Dpart[3 * H + t];
        __syncthreads();

        // --- stage F: hred; pair logits
        if (t < 64) {
            float a = bv1[t];
#pragma unroll
            for (int q = 0; q < 8; q++) a += Vpart[q * 64 + t];
            hred[t] = fmaxf(a, 0.f) * Wv2[t];
        }
        if (t < 486) {
            const int half = (t >= ASL) ? 1 : 0;
            const int pi = t - ASL * half;
            const int pair = pi / 3, bond = pi - pair * 3;
            const int i = pair / NPG, j = pair - i * NPG;
            const float4* Ap = (const float4*)(As + i * 132) + half * 16;
            const float4* Bp = (const float4*)(Bs + j * 132) + half * 16;
            const float4* Dp = (const float4*)Dc + half * 16;
            const float4* Wp = (const float4*)(Wft + bond * H) + half * 16;
            float a = 0.f;
#pragma unroll
            for (int q = 0; q < 16; q++) {
                float4 av = Ap[q], bv = Bp[q], dv = Dp[q], wv = Wp[q];
                a += fmaxf(av.x + bv.x + dv.x, 0.f) * wv.x
                   + fmaxf(av.y + bv.y + dv.y, 0.f) * wv.y
                   + fmaxf(av.z + bv.z + dv.z, 0.f) * wv.z
                   + fmaxf(av.w + bv.w + dv.w, 0.f) * wv.w;
            }
            fp2[t] = a;
        }
        __syncthreads();
        if (t < ASL) fp[t] = fp2[t] + fp2[ASL + t] + bf[t % 3];
        __syncthreads();

        // --- gather + softmax + value out
        float g = -INFINITY;
        if (t < ASL) g = fp[imask[b * ASL + t]] + mask[b * ASL + t];
        float v = g;
#pragma unroll
        for (int off = 16; off; off >>= 1) v = fmaxf(v, __shfl_xor_sync(0xffffffffu, v, off));
        if (lane == 0) red[w] = v;
        __syncthreads();
        if (t == 0) {
            float m = red[0];
#pragma unroll
            for (int i = 1; i < 16; i++) m = fmaxf(m, red[i]);
            rs2[0] = m;
        }
        __syncthreads();
        float e = (t < ASL) ? __expf(g - rs2[0]) : 0.f;
        v = e;
#pragma unroll
        for (int off = 16; off; off >>= 1) v += __shfl_xor_sync(0xffffffffu, v, off);
        if (lane == 0) red[w] = v;
        __syncthreads();
        if (t == 0) {
            float s = 0.f;
#pragma unroll
            for (int i = 0; i < 16; i++) s += red[i];
            rs2[1] = s;
            float vo = bv2[0];
#pragma unroll
            for (int k = 0; k < 64; k++) vo += hred[k];
            out[BATCH * ASL + b] = vo;
        }
        __syncthreads();
        if (t < ASL) out[b * ASL + t] = e / rs2[1];
    }
}

extern "C" void kernel_launch(void* const* d_in, const int* in_sizes, int n_in,
                              void* d_out, int out_size) {
    const float* nf   = (const float*)d_in[0];
    const float* spec = (const float*)d_in[1];
    const float* mask = (const float*)d_in[3];
    const int*   imask= (const int*)  d_in[4];
    const float* W1   = (const float*)d_in[5];
    const float* b1   = (const float*)d_in[6];
    const float* W2   = (const float*)d_in[7];
    const float* b2   = (const float*)d_in[8];
    const float* Wv1  = (const float*)d_in[9];
    const float* bv1  = (const float*)d_in[10];
    const float* Wv2  = (const float*)d_in[11];
    const float* bv2  = (const float*)d_in[12];
    const float* Wa2  = (const float*)d_in[13];
    const float* ba2  = (const float*)d_in[14];
    const float* Wf   = (const float*)d_in[15];
    const float* bf   = (const float*)d_in[16];
    float* out = (float*)d_out;

    fused_kernel<<<NB, THREADS>>>(nf, spec, mask, imask, W1, b1, W2, b2,
                                  Wv1, bv1, Wv2, bv2, Wa2, ba2, Wf, bf, out);
}

// round 12
// speedup vs baseline: 1.1291x; 1.0010x over previous
#include <cuda_runtime.h>
#include <math.h>

#define NB 148
#define THREADS 512
#define BATCH 64
#define NPG 9
#define NTOT (BATCH*NPG)   // 576
#define H 128
#define K1 1801
#define O1 900
#define O2 100
#define ASL 243
#define NT1 15             // 15 n-tiles x 64 outs
#define KS1 9
#define KC1 201            // 9*201 = 1809 >= 1801

// scratch (no allocation allowed)
__device__ float g_s1_part[KS1 * BATCH * O1];
__device__ float g_Ai[NTOT * H];
__device__ float g_Bj[NTOT * H];
__device__ unsigned g_abflag[BATCH];
__device__ unsigned g_count = 0;
__device__ unsigned g_gen = 0;

__device__ __forceinline__ void grid_barrier() {
    __syncthreads();
    __threadfence();
    if (threadIdx.x == 0) {
        unsigned gen = *(volatile unsigned*)&g_gen;
        if (atomicAdd(&g_count, 1u) == NB - 1) {
            g_count = 0;
            __threadfence();
            atomicAdd(&g_gen, 1u);
        } else {
            while (*(volatile unsigned*)&g_gen == gen) __nanosleep(32);
        }
    }
    __syncthreads();
}

__global__ __launch_bounds__(THREADS, 1)
void fused_kernel(const float* __restrict__ nf, const float* __restrict__ spec,
                  const float* __restrict__ mask, const int* __restrict__ imask,
                  const float* __restrict__ W1, const float* __restrict__ b1,
                  const float* __restrict__ W2, const float* __restrict__ b2,
                  const float* __restrict__ Wv1, const float* __restrict__ bv1,
                  const float* __restrict__ Wv2, const float* __restrict__ bv2,
                  const float* __restrict__ Wa2, const float* __restrict__ ba2,
                  const float* __restrict__ Wf, const float* __restrict__ bf,
                  float* __restrict__ out) {
    __shared__ __align__(16) float buf[12288];   // 48KB, reused per phase
    const int t = threadIdx.x;
    const int bid = blockIdx.x;

    // reset per-graph ab flags (ordered before release by grid_barrier's fence)
    if (bid < BATCH && t == 0) g_abflag[bid] = 0;

    // ===== Phase 1: gemm1 only (135 blocks; R8-proven scalar, reg-prefetch) =====
    if (bid < NT1 * KS1) {
        const int nt = bid / KS1, ks = bid % KS1;
        const int og = t & 31;
        const int bg = t >> 5;
        const int o0 = nt * 64 + og * 2;
        const int b0 = bg * 4;
        const int kbeg = ks * KC1;
        const int kend = min(kbeg + KC1, K1);
        const int nch = (kend - kbeg + 31) >> 5;
        float* sp = buf;                     // [32][68]
        float* wt = buf + 32 * 68;           // [32][68]

        const int kk_s = t & 31;
        const int bb_s = t >> 5;
        const int kk_w = t >> 6;
        const int oo_w = t & 63;
        const int ow_g = nt * 64 + oo_w;
        const bool wok = (ow_g < O1);

        float rsv[4], rwv[4];
        {
            const int k0 = kbeg;
            const int klen = kend - k0;
#pragma unroll
            for (int j = 0; j < 4; j++)
                rsv[j] = (kk_s < klen) ? spec[(bb_s + 16 * j) * K1 + k0 + kk_s] : 0.f;
#pragma unroll
            for (int j = 0; j < 4; j++) {
                int kk = kk_w + 8 * j;
                rwv[j] = (kk < klen && wok) ? W1[(k0 + kk) * O1 + ow_g] : 0.f;
            }
        }
        float a00 = 0.f, a01 = 0.f, a10 = 0.f, a11 = 0.f;
        float a20 = 0.f, a21 = 0.f, a30 = 0.f, a31 = 0.f;

        for (int c = 0; c < nch; c++) {
            __syncthreads();
#pragma unroll
            for (int j = 0; j < 4; j++)
                sp[kk_s * 68 + bb_s + 16 * j] = rsv[j];
#pragma unroll
            for (int j = 0; j < 4; j++)
                wt[(kk_w + 8 * j) * 68 + oo_w] = rwv[j];
            __syncthreads();
            if (c + 1 < nch) {
                const int k0 = kbeg + (c + 1) * 32;
                const int klen = kend - k0;
#pragma unroll
                for (int j = 0; j < 4; j++)
                    rsv[j] = (kk_s < klen) ? spec[(bb_s + 16 * j) * K1 + k0 + kk_s] : 0.f;
#pragma unroll
                for (int j = 0; j < 4; j++) {
                    int kk = kk_w + 8 * j;
                    rwv[j] = (kk < klen && wok) ? W1[(k0 + kk) * O1 + ow_g] : 0.f;
                }
            }
#pragma unroll
            for (int kk = 0; kk < 32; kk++) {
                float4 s4 = *(const float4*)(sp + kk * 68 + b0);
                float2 w2 = *(const float2*)(wt + kk * 68 + og * 2);
                a00 += s4.x * w2.x; a01 += s4.x * w2.y;
                a10 += s4.y * w2.x; a11 += s4.y * w2.y;
                a20 += s4.z * w2.x; a21 += s4.z * w2.y;
                a30 += s4.w * w2.x; a31 += s4.w * w2.y;
            }
        }
        float* dst = g_s1_part + ks * (BATCH * O1);
        if (o0 + 1 < O1) {
            dst[(b0 + 0) * O1 + o0] = a00; dst[(b0 + 0) * O1 + o0 + 1] = a01;
            dst[(b0 + 1) * O1 + o0] = a10; dst[(b0 + 1) * O1 + o0 + 1] = a11;
            dst[(b0 + 2) * O1 + o0] = a20; dst[(b0 + 2) * O1 + o0 + 1] = a21;
            dst[(b0 + 3) * O1 + o0] = a30; dst[(b0 + 3) * O1 + o0 + 1] = a31;
        } else if (o0 < O1) {
            dst[(b0 + 0) * O1 + o0] = a00;
            dst[(b0 + 1) * O1 + o0] = a10;
            dst[(b0 + 2) * O1 + o0] = a20;
            dst[(b0 + 3) * O1 + o0] = a30;
        }
    }
    // blocks 135..147 idle in phase 1

    grid_barrier();

    // ===== Phase 2 =====
    if (bid >= 64 && bid < 128) {
        // ---- ab writer for graph b = bid-64: [Ai|Bj] rows -> global + flag ----
        const int b = bid - 64;
        float* nfs_t = buf;           // [128][12] transposed relu(nf)
        float* Pq    = buf + 1536;    // 2304 partials for q=1
        for (int idx = t; idx < NPG * H; idx += THREADS) {
            int i = idx >> 7, k = idx & 127;
            nfs_t[k * 12 + i] = fmaxf(nf[(b * NPG + i) * H + k], 0.f);
        }
        __syncthreads();
        const int c = t & 255, q = t >> 8;
        const int kb = q * 64;
        const float* wbase = Wa2 + ((c < 128) ? c : (H * H + (c - 128)));
        float accp[9];
#pragma unroll
        for (int i = 0; i < 9; i++) accp[i] = 0.f;
#pragma unroll 4
        for (int k = 0; k < 64; k++) {
            const int kg = kb + k;
            float wv = wbase[(size_t)kg * H];
            const float* nr = nfs_t + kg * 12;
            float4 n0 = *(const float4*)nr;
            float4 n1 = *(const float4*)(nr + 4);
            float n8 = nr[8];
            accp[0] += n0.x * wv; accp[1] += n0.y * wv;
            accp[2] += n0.z * wv; accp[3] += n0.w * wv;
            accp[4] += n1.x * wv; accp[5] += n1.y * wv;
            accp[6] += n1.z * wv; accp[7] += n1.w * wv;
            accp[8] += n8 * wv;
        }
        if (q == 1) {
#pragma unroll
            for (int i = 0; i < 9; i++) Pq[c * 9 + i] = accp[i];
        }
        __syncthreads();
        if (q == 0) {
            float* g = (c < 128) ? g_Ai : g_Bj;
            const int cc = (c < 128) ? c : (c - 128);
#pragma unroll
            for (int i = 0; i < 9; i++)
                g[(b * NPG + i) * H + cc] = accp[i] + Pq[c * 9 + i];
        }
        __threadfence();
        __syncthreads();
        if (t == 0) atomicExch(&g_abflag[b], 1u);
    } else if (bid < 64) {
        // ---- per-graph reader: gemm2 -> ss -> D -> value -> pair -> softmax ----
        const int b = bid;
        const int lane = t & 31, w = t >> 5;
        float* s1r   = buf;            // 900 (pad 912)
        float* g2p   = buf + 912;      // 2000 gemm2 partials [20][100]
        float* As    = buf + 2912;     // 9*132
        float* Bs    = buf + 4100;     // 9*132
        float* Wft   = buf + 5288;     // 384 bond-major
        float* x     = buf + 5672;     // 228 (pad 256)
        float* ss    = buf + 5928;     // 100 (pad 128)
        float* Dc    = buf + 6056;     // 128
        float* hred  = buf + 6184;     // 64
        float* fp2   = buf + 6248;     // 486 (pad 512)
        float* fp    = buf + 6760;     // 243 (pad 256)
        float* Dpart = buf + 7016;     // 512
        float* Vpart = buf + 7528;     // 512
        float* red   = buf + 8040;     // 16
        float* rs2   = buf + 8056;     // 2

        // --- stage A: s1r reduce+bias+relu; Wft; readout x[0:128]
        for (int idx = t; idx < O1; idx += THREADS) {
            float v = b1[idx];
#pragma unroll
            for (int c = 0; c < KS1; c++)
                v += g_s1_part[c * (BATCH * O1) + b * O1 + idx];
            s1r[idx] = fmaxf(v, 0.f);
        }
        for (int idx = t; idx < H * 3; idx += THREADS)
            Wft[(idx % 3) * H + idx / 3] = Wf[idx];
        if (t < H) {
            float sum = 0.f;
#pragma unroll
            for (int i = 0; i < NPG; i++) sum += nf[(b * NPG + i) * H + t];
            x[t] = sum;
        }
        __syncthreads();

        // --- stage B: gemm2 partials (t<500): 25 col-quads x 20 k-splits of 45
        if (t < 500) {
            const int oq = t % 25, q = t / 25;
            const int o4 = oq * 4, kb = q * 45;
            float4 acc = make_float4(0.f, 0.f, 0.f, 0.f);
#pragma unroll 5
            for (int kk = 0; kk < 45; kk++) {
                const int k = kb + kk;
                float4 wv = *(const float4*)(W2 + (size_t)k * O2 + o4);
                float s = s1r[k];
                acc.x += s * wv.x; acc.y += s * wv.y;
                acc.z += s * wv.z; acc.w += s * wv.w;
            }
            *(float4*)(g2p + q * O2 + o4) = acc;
        }
        __syncthreads();

        // --- stage C: ss reduce
        if (t < O2) {
            float a = b2[t];
#pragma unroll
            for (int q = 0; q < 20; q++) a += g2p[q * O2 + t];
            ss[t] = fmaxf(a, 0.f);
        }
        __syncthreads();

        // --- wait for ab writer (block b+64)
        if (t == 0) {
            while (atomicAdd(&g_abflag[b], 0u) == 0) __nanosleep(32);
            __threadfence();
        }
        __syncthreads();

        // --- stage D: x tail; As/Bs from global; D partials
        if (t < O2) x[H + t] = ss[t];
        for (int idx = t; idx < NPG * 256; idx += THREADS) {
            int i = idx >> 8, c = idx & 255;
            if (c < 128) As[i * 132 + c] = g_Ai[(b * NPG + i) * H + c];
            else         Bs[i * 132 + c - 128] = g_Bj[(b * NPG + i) * H + c - 128];
        }
        {
            const int o = t & 127, q = t >> 7;
            const int kb = q * 25;
            float d = 0.f;
#pragma unroll
            for (int kk = 0; kk < 25; kk++)
                d += ss[kb + kk] * Wa2[(size_t)(2 * H + kb + kk) * H + o];
            Dpart[q * H + o] = d;
        }
        __syncthreads();

        // --- stage E: V partials; Dc
        {
            const int o = t & 63, q = t >> 6;
            const int kb = q * 29;
            const int kl = min(29, 228 - kb);
            float v = 0.f;
            for (int kk = 0; kk < kl; kk++)
                v += x[kb + kk] * Wv1[(size_t)(kb + kk) * 64 + o];
            Vpart[q * 64 + o] = v;
        }
        if (t < H)
            Dc[t] = ba2[t] + Dpart[t] + Dpart[H + t] + Dpart[2 * H + t] + Dpart[3 * H + t];
        __syncthreads();

        // --- stage F: hred; pair logits
        if (t < 64) {
            float a = bv1[t];
#pragma unroll
            for (int q = 0; q < 8; q++) a += Vpart[q * 64 + t];
            hred[t] = fmaxf(a, 0.f) * Wv2[t];
        }
        if (t < 486) {
            const int half = (t >= ASL) ? 1 : 0;
            const int pi = t - ASL * half;
            const int pair = pi / 3, bond = pi - pair * 3;
            const int i = pair / NPG, j = pair - i * NPG;
            const float4* Ap = (const float4*)(As + i * 132) + half * 16;
            const float4* Bp = (const float4*)(Bs + j * 132) + half * 16;
            const float4* Dp = (const float4*)Dc + half * 16;
            const float4* Wp = (const float4*)(Wft + bond * H) + half * 16;
            float a = 0.f;
#pragma unroll
            for (int q = 0; q < 16; q++) {
                float4 av = Ap[q], bv = Bp[q], dv = Dp[q], wv = Wp[q];
                a += fmaxf(av.x + bv.x + dv.x, 0.f) * wv.x
                   + fmaxf(av.y + bv.y + dv.y, 0.f) * wv.y
                   + fmaxf(av.z + bv.z + dv.z, 0.f) * wv.z
                   + fmaxf(av.w + bv.w + dv.w, 0.f) * wv.w;
            }
            fp2[t] = a;
        }
        __syncthreads();
        if (t < ASL) fp[t] = fp2[t] + fp2[ASL + t] + bf[t % 3];
        __syncthreads();

        // --- gather + softmax + value out
        float g = -INFINITY;
        if (t < ASL) g = fp[imask[b * ASL + t]] + mask[b * ASL + t];
        float v = g;
#pragma unroll
        for (int off = 16; off; off >>= 1) v = fmaxf(v, __shfl_xor_sync(0xffffffffu, v, off));
        if (lane == 0) red[w] = v;
        __syncthreads();
        if (t == 0) {
            float m = red[0];
#pragma unroll
            for (int i = 1; i < 16; i++) m = fmaxf(m, red[i]);
            rs2[0] = m;
        }
        __syncthreads();
        float e = (t < ASL) ? __expf(g - rs2[0]) : 0.f;
        v = e;
#pragma unroll
        for (int off = 16; off; off >>= 1) v += __shfl_xor_sync(0xffffffffu, v, off);
        if (lane == 0) red[w] = v;
        __syncthreads();
        if (t == 0) {
            float s = 0.f;
#pragma unroll
            for (int i = 0; i < 16; i++) s += red[i];
            rs2[1] = s;
            float vo = bv2[0];
#pragma unroll
            for (int k = 0; k < 64; k++) vo += hred[k];
            out[BATCH * ASL + b] = vo;
        }
        __syncthreads();
        if (t < ASL) out[b * ASL + t] = e / rs2[1];
    }
}

extern "C" void kernel_launch(void* const* d_in, const int* in_sizes, int n_in,
                              void* d_out, int out_size) {
    const float* nf   = (const float*)d_in[0];
    const float* spec = (const float*)d_in[1];
    const float* mask = (const float*)d_in[3];
    const int*   imask= (const int*)  d_in[4];
    const float* W1   = (const float*)d_in[5];
    const float* b1   = (const float*)d_in[6];
    const float* W2   = (const float*)d_in[7];
    const float* b2   = (const float*)d_in[8];
    const float* Wv1  = (const float*)d_in[9];
    const float* bv1  = (const float*)d_in[10];
    const float* Wv2  = (const float*)d_in[11];
    const float* bv2  = (const float*)d_in[12];
    const float* Wa2  = (const float*)d_in[13];
    const float* ba2  = (const float*)d_in[14];
    const float* Wf   = (const float*)d_in[15];
    const float* bf   = (const float*)d_in[16];
    float* out = (float*)d_out;

    fused_kernel<<<NB, THREADS>>>(nf, spec, mask, imask, W1, b1, W2, b2,
                                  Wv1, bv1, Wv2, bv2, Wa2, ba2, Wf, bf, out);
}

// round 13
// speedup vs baseline: 1.2169x; 1.0778x over previous
#include <cuda_runtime.h>
#include <math.h>

#define NB 148
#define THREADS 512
#define BATCH 64
#define NPG 9
#define NTOT (BATCH*NPG)   // 576
#define H 128
#define K1 1801
#define O1 900
#define O2 100
#define ASL 243
#define NT1 15             // 15 n-tiles x 64 outs
#define KS1 9
#define KC1 201            // 9*201 = 1809 >= 1801

// scratch (no allocation allowed)
__device__ float g_s1_part[KS1 * BATCH * O1];
__device__ float g_Ai[NTOT * H];
__device__ float g_Bj[NTOT * H];
__device__ unsigned g_abflag[BATCH];
__device__ unsigned g_count = 0;
__device__ unsigned g_gen = 0;

__device__ __forceinline__ void grid_barrier() {
    __syncthreads();
    __threadfence();
    if (threadIdx.x == 0) {
        unsigned gen = *(volatile unsigned*)&g_gen;
        if (atomicAdd(&g_count, 1u) == NB - 1) {
            g_count = 0;
            __threadfence();
            atomicAdd(&g_gen, 1u);
        } else {
            while (*(volatile unsigned*)&g_gen == gen) __nanosleep(32);
        }
    }
    __syncthreads();
}

__global__ __launch_bounds__(THREADS, 1)
void fused_kernel(const float* __restrict__ nf, const float* __restrict__ spec,
                  const float* __restrict__ mask, const int* __restrict__ imask,
                  const float* __restrict__ W1, const float* __restrict__ b1,
                  const float* __restrict__ W2, const float* __restrict__ b2,
                  const float* __restrict__ Wv1, const float* __restrict__ bv1,
                  const float* __restrict__ Wv2, const float* __restrict__ bv2,
                  const float* __restrict__ Wa2, const float* __restrict__ ba2,
                  const float* __restrict__ Wf, const float* __restrict__ bf,
                  float* __restrict__ out) {
    __shared__ __align__(16) float buf[12288];   // 48KB, reused per phase
    const int t = threadIdx.x;
    const int bid = blockIdx.x;

    // reset per-graph ab flags (ordered before release by grid_barrier's fence)
    if (bid < BATCH && t == 0) g_abflag[bid] = 0;

    // ===== Phase 1: gemm1 only (135 blocks; scalar, reg-prefetch, sw-pipelined) =====
    if (bid < NT1 * KS1) {
        const int nt = bid / KS1, ks = bid % KS1;
        const int og = t & 31;
        const int bg = t >> 5;
        const int o0 = nt * 64 + og * 2;
        const int b0 = bg * 4;
        const int kbeg = ks * KC1;
        const int kend = min(kbeg + KC1, K1);
        const int nch = (kend - kbeg + 31) >> 5;
        float* sp = buf;                     // [32][68]
        float* wt = buf + 32 * 68;           // [32][68]

        const int kk_s = t & 31;
        const int bb_s = t >> 5;
        const int kk_w = t >> 6;
        const int oo_w = t & 63;
        const int ow_g = nt * 64 + oo_w;
        const bool wok = (ow_g < O1);

        float rsv[4], rwv[4];
        {
            const int k0 = kbeg;
            const int klen = kend - k0;
#pragma unroll
            for (int j = 0; j < 4; j++)
                rsv[j] = (kk_s < klen) ? spec[(bb_s + 16 * j) * K1 + k0 + kk_s] : 0.f;
#pragma unroll
            for (int j = 0; j < 4; j++) {
                int kk = kk_w + 8 * j;
                rwv[j] = (kk < klen && wok) ? W1[(k0 + kk) * O1 + ow_g] : 0.f;
            }
        }
        float a00 = 0.f, a01 = 0.f, a10 = 0.f, a11 = 0.f;
        float a20 = 0.f, a21 = 0.f, a30 = 0.f, a31 = 0.f;

        for (int c = 0; c < nch; c++) {
            __syncthreads();
#pragma unroll
            for (int j = 0; j < 4; j++)
                sp[kk_s * 68 + bb_s + 16 * j] = rsv[j];
#pragma unroll
            for (int j = 0; j < 4; j++)
                wt[(kk_w + 8 * j) * 68 + oo_w] = rwv[j];
            __syncthreads();
            if (c + 1 < nch) {
                const int k0 = kbeg + (c + 1) * 32;
                const int klen = kend - k0;
#pragma unroll
                for (int j = 0; j < 4; j++)
                    rsv[j] = (kk_s < klen) ? spec[(bb_s + 16 * j) * K1 + k0 + kk_s] : 0.f;
#pragma unroll
                for (int j = 0; j < 4; j++) {
                    int kk = kk_w + 8 * j;
                    rwv[j] = (kk < klen && wok) ? W1[(k0 + kk) * O1 + ow_g] : 0.f;
                }
            }
            // software-pipelined: issue kk+1 loads before kk FMAs
            float4 s4 = *(const float4*)(sp + b0);
            float2 w2 = *(const float2*)(wt + og * 2);
#pragma unroll
            for (int kk = 0; kk < 32; kk++) {
                float4 s4c = s4;
                float2 w2c = w2;
                if (kk < 31) {
                    s4 = *(const float4*)(sp + (kk + 1) * 68 + b0);
                    w2 = *(const float2*)(wt + (kk + 1) * 68 + og * 2);
                }
                a00 += s4c.x * w2c.x; a01 += s4c.x * w2c.y;
                a10 += s4c.y * w2c.x; a11 += s4c.y * w2c.y;
                a20 += s4c.z * w2c.x; a21 += s4c.z * w2c.y;
                a30 += s4c.w * w2c.x; a31 += s4c.w * w2c.y;
            }
        }
        float* dst = g_s1_part + ks * (BATCH * O1);
        if (o0 + 1 < O1) {
            dst[(b0 + 0) * O1 + o0] = a00; dst[(b0 + 0) * O1 + o0 + 1] = a01;
            dst[(b0 + 1) * O1 + o0] = a10; dst[(b0 + 1) * O1 + o0 + 1] = a11;
            dst[(b0 + 2) * O1 + o0] = a20; dst[(b0 + 2) * O1 + o0 + 1] = a21;
            dst[(b0 + 3) * O1 + o0] = a30; dst[(b0 + 3) * O1 + o0 + 1] = a31;
        } else if (o0 < O1) {
            dst[(b0 + 0) * O1 + o0] = a00;
            dst[(b0 + 1) * O1 + o0] = a10;
            dst[(b0 + 2) * O1 + o0] = a20;
            dst[(b0 + 3) * O1 + o0] = a30;
        }
    }

    grid_barrier();

    // ===== Phase 2 =====
    if (bid >= 64 && bid < 128) {
        // ---- ab writer for graph b = bid-64 ----
        const int b = bid - 64;
        float* nfs_t = buf;           // [128][12] transposed relu(nf)
        float* Pq    = buf + 1536;    // 2304 partials for q=1
        for (int idx = t; idx < NPG * H; idx += THREADS) {
            int i = idx >> 7, k = idx & 127;
            nfs_t[k * 12 + i] = fmaxf(nf[(b * NPG + i) * H + k], 0.f);
        }
        __syncthreads();
        const int c = t & 255, q = t >> 8;
        const int kb = q * 64;
        const float* wbase = Wa2 + ((c < 128) ? c : (H * H + (c - 128)));
        float accp[9];
#pragma unroll
        for (int i = 0; i < 9; i++) accp[i] = 0.f;
#pragma unroll 4
        for (int k = 0; k < 64; k++) {
            const int kg = kb + k;
            float wv = wbase[(size_t)kg * H];
            const float* nr = nfs_t + kg * 12;
            float4 n0 = *(const float4*)nr;
            float4 n1 = *(const float4*)(nr + 4);
            float n8 = nr[8];
            accp[0] += n0.x * wv; accp[1] += n0.y * wv;
            accp[2] += n0.z * wv; accp[3] += n0.w * wv;
            accp[4] += n1.x * wv; accp[5] += n1.y * wv;
            accp[6] += n1.z * wv; accp[7] += n1.w * wv;
            accp[8] += n8 * wv;
        }
        if (q == 1) {
#pragma unroll
            for (int i = 0; i < 9; i++) Pq[c * 9 + i] = accp[i];
        }
        __syncthreads();
        if (q == 0) {
            float* g = (c < 128) ? g_Ai : g_Bj;
            const int cc = (c < 128) ? c : (c - 128);
#pragma unroll
            for (int i = 0; i < 9; i++)
                g[(b * NPG + i) * H + cc] = accp[i] + Pq[c * 9 + i];
        }
        __threadfence();
        __syncthreads();
        if (t == 0) atomicExch(&g_abflag[b], 1u);
    } else if (bid < 64) {
        // ---- per-graph reader ----
        const int b = bid;
        const int lane = t & 31, w = t >> 5;
        float* s1r   = buf;            // 900 (pad 912)
        float* g2p   = buf + 912;      // 2000 gemm2 partials [20][100]
        float* As    = buf + 2912;     // 9*132
        float* Bs    = buf + 4100;     // 9*132
        float* Wft   = buf + 5288;     // 384 bond-major
        float* x     = buf + 5672;     // 232 used (pad 256)
        float* ss    = buf + 5928;     // 100 (pad 128)
        float* Dc    = buf + 6056;     // 128
        float* hred  = buf + 6184;     // 2 (warp sums)
        float* fp2   = buf + 6248;     // 486 (pad 512)
        float* fp    = buf + 6760;     // 243 (pad 256)
        float* Dpart = buf + 7016;     // 512
        float* Vpart = buf + 7528;     // 512
        float* red   = buf + 8040;     // 16
        float* rs2   = buf + 8056;     // 2

        // --- stage A: s1r reduce+bias+relu; Wft; readout x[0:128]; x pad zeros
        for (int idx = t; idx < O1; idx += THREADS) {
            float v = b1[idx];
#pragma unroll
            for (int c = 0; c < KS1; c++)
                v += g_s1_part[c * (BATCH * O1) + b * O1 + idx];
            s1r[idx] = fmaxf(v, 0.f);
        }
        for (int idx = t; idx < H * 3; idx += THREADS)
            Wft[(idx % 3) * H + idx / 3] = Wf[idx];
        if (t < H) {
            float sum = 0.f;
#pragma unroll
            for (int i = 0; i < NPG; i++) sum += nf[(b * NPG + i) * H + t];
            x[t] = sum;
        }
        if (t >= 228 && t < 232) x[t] = 0.f;   // pad for uniform Vpart loop
        __syncthreads();

        // --- stage B: gemm2 partials, fully unrolled for MLP
        if (t < 500) {
            const int oq = t % 25, q = t / 25;
            const int o4 = oq * 4, kb = q * 45;
            float4 acc = make_float4(0.f, 0.f, 0.f, 0.f);
#pragma unroll
            for (int kk = 0; kk < 45; kk++) {
                const int k = kb + kk;
                float4 wv = *(const float4*)(W2 + (size_t)k * O2 + o4);
                float s = s1r[k];
                acc.x += s * wv.x; acc.y += s * wv.y;
                acc.z += s * wv.z; acc.w += s * wv.w;
            }
            *(float4*)(g2p + q * O2 + o4) = acc;
        }
        __syncthreads();

        // --- stage C: ss reduce
        if (t < O2) {
            float a = b2[t];
#pragma unroll
            for (int q = 0; q < 20; q++) a += g2p[q * O2 + t];
            ss[t] = fmaxf(a, 0.f);
        }
        __syncthreads();

        // --- wait for ab writer (block b+64)
        if (t == 0) {
            while (atomicAdd(&g_abflag[b], 0u) == 0) __nanosleep(32);
            __threadfence();
        }
        __syncthreads();

        // --- stage D: x tail; As/Bs from global; D partials
        if (t < O2) x[H + t] = ss[t];
        for (int idx = t; idx < NPG * 256; idx += THREADS) {
            int i = idx >> 8, c = idx & 255;
            if (c < 128) As[i * 132 + c] = g_Ai[(b * NPG + i) * H + c];
            else         Bs[i * 132 + c - 128] = g_Bj[(b * NPG + i) * H + c - 128];
        }
        {
            const int o = t & 127, q = t >> 7;
            const int kb = q * 25;
            float d = 0.f;
#pragma unroll
            for (int kk = 0; kk < 25; kk++)
                d += ss[kb + kk] * Wa2[(size_t)(2 * H + kb + kk) * H + o];
            Dpart[q * H + o] = d;
        }
        __syncthreads();

        // --- stage E: V partials (uniform 29, fully unrolled); Dc
        {
            const int o = t & 63, q = t >> 6;
            const int kb = q * 29;
            float v = 0.f;
#pragma unroll
            for (int kk = 0; kk < 29; kk++)
                v += x[kb + kk] * Wv1[(size_t)(kb + kk) * 64 + o];
            Vpart[q * 64 + o] = v;
        }
        if (t < H)
            Dc[t] = ba2[t] + Dpart[t] + Dpart[H + t] + Dpart[2 * H + t] + Dpart[3 * H + t];
        __syncthreads();

        // --- stage F: value hidden (shuffle-reduced); pair logits
        if (t < 64) {
            float a = bv1[t];
#pragma unroll
            for (int q = 0; q < 8; q++) a += Vpart[q * 64 + t];
            float hv = fmaxf(a, 0.f) * Wv2[t];
#pragma unroll
            for (int off = 16; off; off >>= 1)
                hv += __shfl_xor_sync(0xffffffffu, hv, off);
            if ((t & 31) == 0) hred[t >> 5] = hv;
        }
        if (t < 486) {
            const int half = (t >= ASL) ? 1 : 0;
            const int pi = t - ASL * half;
            const int pair = pi / 3, bond = pi - pair * 3;
            const int i = pair / NPG, j = pair - i * NPG;
            const float4* Ap = (const float4*)(As + i * 132) + half * 16;
            const float4* Bp = (const float4*)(Bs + j * 132) + half * 16;
            const float4* Dp = (const float4*)Dc + half * 16;
            const float4* Wp = (const float4*)(Wft + bond * H) + half * 16;
            float a = 0.f;
#pragma unroll
            for (int q = 0; q < 16; q++) {
                float4 av = Ap[q], bv = Bp[q], dv = Dp[q], wv = Wp[q];
                a += fmaxf(av.x + bv.x + dv.x, 0.f) * wv.x
                   + fmaxf(av.y + bv.y + dv.y, 0.f) * wv.y
                   + fmaxf(av.z + bv.z + dv.z, 0.f) * wv.z
                   + fmaxf(av.w + bv.w + dv.w, 0.f) * wv.w;
            }
            fp2[t] = a;
        }
        __syncthreads();
        if (t < ASL) fp[t] = fp2[t] + fp2[ASL + t] + bf[t % 3];
        __syncthreads();

        // --- gather + softmax + value out
        float g = -INFINITY;
        if (t < ASL) g = fp[imask[b * ASL + t]] + mask[b * ASL + t];
        float v = g;
#pragma unroll
        for (int off = 16; off; off >>= 1) v = fmaxf(v, __shfl_xor_sync(0xffffffffu, v, off));
        if (lane == 0) red[w] = v;
        __syncthreads();
        if (t == 0) {
            float m = red[0];
#pragma unroll
            for (int i = 1; i < 16; i++) m = fmaxf(m, red[i]);
            rs2[0] = m;
        }
        __syncthreads();
        float e = (t < ASL) ? __expf(g - rs2[0]) : 0.f;
        v = e;
#pragma unroll
        for (int off = 16; off; off >>= 1) v += __shfl_xor_sync(0xffffffffu, v, off);
        if (lane == 0) red[w] = v;
        __syncthreads();
        if (t == 0) {
            float s = 0.f;
#pragma unroll
            for (int i = 0; i < 16; i++) s += red[i];
            rs2[1] = s;
            out[BATCH * ASL + b] = bv2[0] + hred[0] + hred[1];
        }
        __syncthreads();
        if (t < ASL) out[b * ASL + t] = e / rs2[1];
    }
}

extern "C" void kernel_launch(void* const* d_in, const int* in_sizes, int n_in,
                              void* d_out, int out_size) {
    const float* nf   = (const float*)d_in[0];
    const float* spec = (const float*)d_in[1];
    const float* mask = (const float*)d_in[3];
    const int*   imask= (const int*)  d_in[4];
    const float* W1   = (const float*)d_in[5];
    const float* b1   = (const float*)d_in[6];
    const float* W2   = (const float*)d_in[7];
    const float* b2   = (const float*)d_in[8];
    const float* Wv1  = (const float*)d_in[9];
    const float* bv1  = (const float*)d_in[10];
    const float* Wv2  = (const float*)d_in[11];
    const float* bv2  = (const float*)d_in[12];
    const float* Wa2  = (const float*)d_in[13];
    const float* ba2  = (const float*)d_in[14];
    const float* Wf   = (const float*)d_in[15];
    const float* bf   = (const float*)d_in[16];
    float* out = (float*)d_out;

    fused_kernel<<<NB, THREADS>>>(nf, spec, mask, imask, W1, b1, W2, b2,
                                  Wv1, bv1, Wv2, bv2, Wa2, ba2, Wf, bf, out);
}